// round 16
// baseline (speedup 1.0000x reference)
#include <cuda_runtime.h>
#include <math.h>

#define NTOK 4096
#define DIM  1024
#define NEXP 8
#define CAP  1280
#define NSLOT (NTOK * 2)
#define ROWW (NEXP * CAP)            // 10240 floats per mask token-row

#define B_ZERO 2048                  // mask zero-fill blocks (80 KB each)
#define B_LOG  512                   // logits blocks, 1 token/warp
#define B_BAT  (NEXP * CAP / 2)      // 5120 batch blocks, 2 rows each
#define NBLK2  (B_BAT + NSLOT / 256) // 5152

// Scratch (no device allocs). No flags/sentinels — graph edges give ordering.
__device__ int g_topidx[NSLOT];      // expert id per slot
__device__ int g_pos[NSLOT];         // packed e*CAP+p, or -1 if dropped
__device__ int g_inv[NEXP * CAP];    // (e,pos) -> token, -1 if empty

// ---------------------------------------------------------------------------
// Branch A: zero the mask. Pure streaming stores (proven ~6.8 TB/s shape).
// ---------------------------------------------------------------------------
__global__ __launch_bounds__(256) void k_zero(float* __restrict__ mask) {
    float4* dst = (float4*)mask + (size_t)blockIdx.x * (256 * 20) + threadIdx.x;
    const float4 z = make_float4(0.f, 0.f, 0.f, 0.f);
#pragma unroll
    for (int j = 0; j < 20; j++)
        __stcs(dst + j * 256, z);
}

// ---------------------------------------------------------------------------
// Branch B1: logits. 1 token/warp, x + W from global (W broadcast -> L1).
// Lean: no smem, no fences, no atomics (proven R14 shape, ~38 regs).
// ---------------------------------------------------------------------------
__global__ __launch_bounds__(256) void k_logits(const float* __restrict__ x,
                                                const float* __restrict__ Wg,
                                                float* __restrict__ gates) {
    int warp = threadIdx.x >> 5;
    int lane = threadIdx.x & 31;
    int t = blockIdx.x * 8 + warp;

    const float4* xr = (const float4*)x + (size_t)t * (DIM / 4);
    const float4* W4 = (const float4*)Wg;

    float acc[NEXP];
#pragma unroll
    for (int e = 0; e < NEXP; e++) acc[e] = 0.f;

#pragma unroll
    for (int i = 0; i < 8; i++) {
        int o = lane + 32 * i;
        float4 v = xr[o];
#pragma unroll
        for (int e = 0; e < NEXP; e++) {
            float4 w = W4[e * 256 + o];
            acc[e] += v.x * w.x + v.y * w.y + v.z * w.z + v.w * w.w;
        }
    }
#pragma unroll
    for (int off = 16; off; off >>= 1)
#pragma unroll
        for (int e = 0; e < NEXP; e++)
            acc[e] += __shfl_xor_sync(0xffffffffu, acc[e], off);

    if (lane == 0) {
        float v1 = -1e30f, v2 = -1e30f;
        int i1 = 0, i2 = 0;
#pragma unroll
        for (int e = 0; e < NEXP; e++) {
            float a = acc[e];
            if (a > v1)      { v2 = v1; i2 = i1; v1 = a; i1 = e; }
            else if (a > v2) { v2 = a;  i2 = e; }
        }
        float e2 = expf(v2 - v1);
        float inv = 1.f / (1.f + e2);
        gates[2 * t]     = inv;
        gates[2 * t + 1] = e2 * inv;
        g_topidx[2 * t]     = i1;
        g_topidx[2 * t + 1] = i2;
    }
}

// ---------------------------------------------------------------------------
// Branch B2: scan (1 block). Positions + inverse map. Stream-ordered after
// k_logits; free to use registers — it's its own kernel.
// ---------------------------------------------------------------------------
__global__ __launch_bounds__(256) void k_scan() {
    __shared__ uint4 ssc[256];
    int tid = threadIdx.x;

    for (int i = tid; i < NEXP * CAP; i += 256) g_inv[i] = -1;

    int base = tid * 32;
    int e_loc[32];
    unsigned short h[NEXP];
#pragma unroll
    for (int e = 0; e < NEXP; e++) h[e] = 0;
#pragma unroll
    for (int j = 0; j < 32; j++) {
        int e = g_topidx[base + j];
        e_loc[j] = e;
        h[e]++;
    }

    uint4 v;
    v.x = (unsigned)h[0] | ((unsigned)h[1] << 16);
    v.y = (unsigned)h[2] | ((unsigned)h[3] << 16);
    v.z = (unsigned)h[4] | ((unsigned)h[5] << 16);
    v.w = (unsigned)h[6] | ((unsigned)h[7] << 16);
    ssc[tid] = v;
    __syncthreads();
    for (int off = 1; off < 256; off <<= 1) {
        uint4 a = make_uint4(0, 0, 0, 0);
        if (tid >= off) a = ssc[tid - off];
        __syncthreads();
        v.x += a.x; v.y += a.y; v.z += a.z; v.w += a.w;
        ssc[tid] = v;
        __syncthreads();
    }

    int cnt[NEXP];
    cnt[0] = (int)(v.x & 0xFFFF) - (int)h[0];
    cnt[1] = (int)(v.x >> 16)    - (int)h[1];
    cnt[2] = (int)(v.y & 0xFFFF) - (int)h[2];
    cnt[3] = (int)(v.y >> 16)    - (int)h[3];
    cnt[4] = (int)(v.z & 0xFFFF) - (int)h[4];
    cnt[5] = (int)(v.z >> 16)    - (int)h[5];
    cnt[6] = (int)(v.w & 0xFFFF) - (int)h[6];
    cnt[7] = (int)(v.w >> 16)    - (int)h[7];

#pragma unroll
    for (int j = 0; j < 32; j++) {
        int slot = base + j;
        int e = e_loc[j];
        int p = cnt[e]++;
        if (p < CAP) {
            g_pos[slot] = e * CAP + p;               // packed offset
            g_inv[e * CAP + p] = slot >> 1;
        } else {
            g_pos[slot] = -1;
        }
    }
}

// ---------------------------------------------------------------------------
// Join node: exp_batches (2 rows/block) + gate scatter into zeroed mask.
// Runs after BOTH k_zero (event edge) and k_scan (stream edge). Proven 12.1us.
// ---------------------------------------------------------------------------
__global__ __launch_bounds__(256) void k_out(const float* __restrict__ x,
                                             const float* __restrict__ gates,
                                             float* __restrict__ mask,
                                             float* __restrict__ batch) {
    int b = blockIdx.x;

    if (b < B_BAT) {
        int r0 = b * 2;
#pragma unroll
        for (int j = 0; j < 2; j++) {
            int r = r0 + j;
            int t = g_inv[r];
            float4 v = make_float4(0.f, 0.f, 0.f, 0.f);
            if (t >= 0)
                v = ((const float4*)x)[(size_t)t * (DIM / 4) + threadIdx.x];
            __stcs((float4*)batch + (size_t)r * (DIM / 4) + threadIdx.x, v);
        }
    } else {
        int slot = (b - B_BAT) * 256 + threadIdx.x;  // 0 .. NSLOT-1
        int off = g_pos[slot];
        if (off >= 0) {
            int tok = slot >> 1;
            mask[(size_t)tok * ROWW + off] = gates[slot];
        }
    }
}

// ---------------------------------------------------------------------------
// Graph-forked launch: zero-fill runs CONCURRENTLY with logits+scan.
//
//   default stream:  [eFork]--- k_logits --- k_scan ---[wait eJoin]--- k_out
//   s1 (forked):        \----- k_zero ------[eJoin]------/
//
// Streams/events are host-side handles (no device memory). They are created
// fresh per call and intentionally not destroyed (kernel_launch runs only a
// few times; destroying mid-capture risks invalidating the capture).
// ---------------------------------------------------------------------------
extern "C" void kernel_launch(void* const* d_in, const int* in_sizes, int n_in,
                              void* d_out, int out_size) {
    const float* x  = (const float*)d_in[0];   // [2,2048,1024] f32
    const float* Wg = (const float*)d_in[1];   // [8,1024] f32

    float* out   = (float*)d_out;
    float* gates = out;                                  // 8,192 floats
    float* mask  = out + (size_t)NSLOT;                  // 41,943,040 floats
    float* batch = mask + (size_t)NTOK * ROWW;           // 10,485,760 floats

    cudaStream_t s1;
    cudaStreamCreateWithFlags(&s1, cudaStreamNonBlocking);
    cudaEvent_t eFork, eJoin;
    cudaEventCreateWithFlags(&eFork, cudaEventDisableTiming);
    cudaEventCreateWithFlags(&eJoin, cudaEventDisableTiming);

    // fork: k_zero on s1, concurrent with logits+scan on the default stream
    cudaEventRecord(eFork, 0);
    cudaStreamWaitEvent(s1, eFork, 0);
    k_zero<<<B_ZERO, 256, 0, s1>>>(mask);
    cudaEventRecord(eJoin, s1);

    k_logits<<<B_LOG, 256>>>(x, Wg, gates);
    k_scan<<<1, 256>>>();

    // join: k_out needs both the zeroed mask and the scan results
    cudaStreamWaitEvent(0, eJoin, 0);
    k_out<<<NBLK2, 256>>>(x, gates, mask, batch);
}

// round 17
// speedup vs baseline: 1.5763x; 1.5763x over previous
#include <cuda_runtime.h>
#include <math.h>

#define NTOK 4096
#define DIM  1024
#define NEXP 8
#define CAP  1280
#define NSLOT (NTOK * 2)
#define ROWW (NEXP * CAP)            // 10240 floats per mask token-row

// ---- node 1: logits (0..511) + zero-fill (512..2559)
#define B_LOG  512                   // 8 tokens (16 slots) per block
#define B_ZERO 2048
#define NBLK1  (B_LOG + B_ZERO)

// ---- node 2: slot-blocks (0..511) + empty-row blocks (512..1791)
#define B_EMPT 1280                  // 8 batch rows each
#define NBLK2  (B_LOG + B_EMPT)

// Stateless scratch: overwritten every launch, no resets, no flags.
__device__ int g_topidx[NSLOT];                  // expert id per slot
__device__ __align__(16) int g_hist[B_LOG][NEXP]; // per-logits-block histogram

// ---------------------------------------------------------------------------
// Node 1: lean logits + per-block histogram + mask zero-fill (proven 30.3us).
// ---------------------------------------------------------------------------
__global__ __launch_bounds__(256) void k_pre(const float* __restrict__ x,
                                             const float* __restrict__ Wg,
                                             float* __restrict__ gates,
                                             float* __restrict__ mask) {
    __shared__ int sm_e[16];                     // 64 B — logits branch only
    const int b = blockIdx.x;

    if (b >= B_LOG) {
        // ----- mask zero-fill: stores only -----
        int zb = b - B_LOG;
        float4* dst = (float4*)mask + (size_t)zb * (256 * 20) + threadIdx.x;
        const float4 z = make_float4(0.f, 0.f, 0.f, 0.f);
#pragma unroll
        for (int j = 0; j < 20; j++)
            __stcs(dst + j * 256, z);
        return;
    }

    // ----- logits: 1 token/warp, x + W from global (W broadcast -> L1) -----
    int warp = threadIdx.x >> 5;
    int lane = threadIdx.x & 31;
    int t = b * 8 + warp;

    const float4* xr = (const float4*)x + (size_t)t * (DIM / 4);
    const float4* W4 = (const float4*)Wg;

    float acc[NEXP];
#pragma unroll
    for (int e = 0; e < NEXP; e++) acc[e] = 0.f;

#pragma unroll
    for (int i = 0; i < 8; i++) {
        int o = lane + 32 * i;
        float4 v = xr[o];
#pragma unroll
        for (int e = 0; e < NEXP; e++) {
            float4 w = W4[e * 256 + o];
            acc[e] += v.x * w.x + v.y * w.y + v.z * w.z + v.w * w.w;
        }
    }
#pragma unroll
    for (int off = 16; off; off >>= 1)
#pragma unroll
        for (int e = 0; e < NEXP; e++)
            acc[e] += __shfl_xor_sync(0xffffffffu, acc[e], off);

    if (lane == 0) {
        float v1 = -1e30f, v2 = -1e30f;
        int i1 = 0, i2 = 0;
#pragma unroll
        for (int e = 0; e < NEXP; e++) {
            float a = acc[e];
            if (a > v1)      { v2 = v1; i2 = i1; v1 = a; i1 = e; }
            else if (a > v2) { v2 = a;  i2 = e; }
        }
        float e2 = expf(v2 - v1);
        float inv = 1.f / (1.f + e2);
        gates[2 * t]     = inv;
        gates[2 * t + 1] = e2 * inv;
        g_topidx[2 * t]     = i1;
        g_topidx[2 * t + 1] = i2;
        sm_e[2 * warp]     = i1;
        sm_e[2 * warp + 1] = i2;
    }
    __syncthreads();
    if (threadIdx.x < NEXP) {                    // block histogram, overwrite
        int c = 0;
#pragma unroll
        for (int j = 0; j < 16; j++) c += (sm_e[j] == (int)threadIdx.x);
        g_hist[b][threadIdx.x] = c;
    }
}

// ---------------------------------------------------------------------------
// Shared helper: block-parallel sum of g_hist rows [0, nb) into sm_pre[8].
// ---------------------------------------------------------------------------
__device__ __forceinline__ void hist_prefix(int nb, int* sm_pre, int* sm_w) {
    int acc[NEXP];
#pragma unroll
    for (int e = 0; e < NEXP; e++) acc[e] = 0;
    for (int i = threadIdx.x; i < nb; i += 256) {
        const int4* hp = (const int4*)g_hist[i];
        int4 a = hp[0], c = hp[1];
        acc[0] += a.x; acc[1] += a.y; acc[2] += a.z; acc[3] += a.w;
        acc[4] += c.x; acc[5] += c.y; acc[6] += c.z; acc[7] += c.w;
    }
#pragma unroll
    for (int off = 16; off; off >>= 1)
#pragma unroll
        for (int e = 0; e < NEXP; e++)
            acc[e] += __shfl_xor_sync(0xffffffffu, acc[e], off);
    int warp = threadIdx.x >> 5;
    if ((threadIdx.x & 31) == 0)
#pragma unroll
        for (int e = 0; e < NEXP; e++) sm_w[warp * NEXP + e] = acc[e];
    __syncthreads();
    if (threadIdx.x < NEXP) {
        int s = 0;
#pragma unroll
        for (int w = 0; w < 8; w++) s += sm_w[w * NEXP + threadIdx.x];
        sm_pre[threadIdx.x] = s;
    }
    __syncthreads();
}

// ---------------------------------------------------------------------------
// Node 2: stateless finish. Slot-blocks: recompute positions for one logits
// block, copy batch rows, write gates into mask. Empty-blocks: zero the
// unoccupied batch rows. No sync, no atomics, no ordering inside the node.
// ---------------------------------------------------------------------------
__global__ __launch_bounds__(256) void k_fin(const float* __restrict__ x,
                                             const float* __restrict__ gates,
                                             float* __restrict__ mask,
                                             float* __restrict__ batch) {
    __shared__ int sm_w[8 * NEXP];
    __shared__ int sm_pre[NEXP];
    __shared__ int sm_e[16], sm_p[16];
    const int b = blockIdx.x;

    if (b < B_LOG) {
        // ---- slot-block for logits block b: slots [16b, 16b+16) ----
        hist_prefix(b, sm_pre, sm_w);            // prefix over blocks < b

        if (threadIdx.x < 16)
            sm_e[threadIdx.x] = g_topidx[16 * b + threadIdx.x];
        __syncthreads();

        if (threadIdx.x == 0) {                  // serial rank of 16 slots
            int run[NEXP];
#pragma unroll
            for (int e = 0; e < NEXP; e++) run[e] = 0;
#pragma unroll
            for (int l = 0; l < 16; l++) {
                int e = sm_e[l];
                sm_p[l] = sm_pre[e] + run[e];
                run[e]++;
            }
        }
        __syncthreads();

#pragma unroll
        for (int l = 0; l < 16; l++) {
            int p = sm_p[l];
            if (p < CAP) {
                int e = sm_e[l];
                int slot = 16 * b + l;
                int tok = slot >> 1;
                int r = e * CAP + p;
                // batch row copy
                float4 v = ((const float4*)x)[(size_t)tok * (DIM / 4) + threadIdx.x];
                __stcs((float4*)batch + (size_t)r * (DIM / 4) + threadIdx.x, v);
                // gate into zeroed mask
                if (threadIdx.x == 0)
                    mask[(size_t)tok * ROWW + r] = gates[slot];
            }
        }
        return;
    }

    // ---- empty-row block: totals, then zero rows with p >= total[e] ----
    hist_prefix(B_LOG, sm_pre, sm_w);            // full totals
    int r0 = (b - B_LOG) * 8;
#pragma unroll
    for (int j = 0; j < 8; j++) {
        int r = r0 + j;
        int e = r / CAP;
        int p = r - e * CAP;
        if (p >= sm_pre[e]) {                    // unoccupied -> zero
            const float4 z = make_float4(0.f, 0.f, 0.f, 0.f);
            __stcs((float4*)batch + (size_t)r * (DIM / 4) + threadIdx.x, z);
        }
    }
}

// ---------------------------------------------------------------------------
extern "C" void kernel_launch(void* const* d_in, const int* in_sizes, int n_in,
                              void* d_out, int out_size) {
    const float* x  = (const float*)d_in[0];   // [2,2048,1024] f32
    const float* Wg = (const float*)d_in[1];   // [8,1024] f32

    float* out   = (float*)d_out;
    float* gates = out;                                  // 8,192 floats
    float* mask  = out + (size_t)NSLOT;                  // 41,943,040 floats
    float* batch = mask + (size_t)NTOK * ROWW;           // 10,485,760 floats

    k_pre<<<NBLK1, 256>>>(x, Wg, gates, mask);
    k_fin<<<NBLK2, 256>>>(x, gates, mask, batch);
}